// round 6
// baseline (speedup 1.0000x reference)
#include <cuda_runtime.h>
#include <cuda_bf16.h>
#include <mma.h>
#include <cstdint>

using namespace nvcuda;

// Fixed shapes
#define B_      2
#define L_      512
#define D_      256
#define TILE    64
#define THREADS 512
#define SST     264                      // 256 + 8 pad bf16 (528B rows)
#define TILE_ELEMS (TILE * SST)
#define SMEM_BYTES (4 * TILE_ELEMS * 2)  // 135168 B

// out[b,i,j] = sum_d x[b,i,d]*w1[d]*x[b,j,d] + bias
// (lin_i - lin_j cancels under (P+P^T)/2 symmetrization; w2 dead.)
// split-bf16 3-product: a*x ≈ ahi*xhi + ahi*xlo + alo*xhi (rel ~2^-18)

// pack 2 floats -> bf16x2 (1 CVT)
__device__ __forceinline__ uint32_t cvt2(float a, float b) {
    __nv_bfloat162 h = __floats2bfloat162_rn(a, b);
    return *reinterpret_cast<uint32_t*>(&h);
}

// split 4 floats -> (hi bf16x4 as uint2, lo bf16x4 as uint2)
__device__ __forceinline__ void split4(const float* v, uint2& hi, uint2& lo) {
    uint32_t h01 = cvt2(v[0], v[1]);
    uint32_t h23 = cvt2(v[2], v[3]);
    // exact f32 of each bf16: low half shifted up / high half masked
    float f0 = __uint_as_float(h01 << 16);
    float f1 = __uint_as_float(h01 & 0xFFFF0000u);
    float f2 = __uint_as_float(h23 << 16);
    float f3 = __uint_as_float(h23 & 0xFFFF0000u);
    hi.x = h01; hi.y = h23;
    lo.x = cvt2(v[0] - f0, v[1] - f1);
    lo.y = cvt2(v[2] - f2, v[3] - f3);
}

__global__ __launch_bounds__(THREADS, 1)
void fused_pairwise_kernel(const float* __restrict__ x,
                           const float* __restrict__ W,
                           const float* __restrict__ bias_p,
                           float* __restrict__ out) {
    extern __shared__ __align__(16) __nv_bfloat16 smem[];
    __nv_bfloat16* sAhi = smem;
    __nv_bfloat16* sAlo = smem + TILE_ELEMS;
    __nv_bfloat16* sBhi = smem + 2 * TILE_ELEMS;
    __nv_bfloat16* sBlo = smem + 3 * TILE_ELEMS;

    const int bz  = blockIdx.z;
    const int ti  = blockIdx.y;
    const int tj  = blockIdx.x;
    const int tid = threadIdx.x;
    const int warp = tid >> 5;
    const int wr = warp >> 2;     // 0..3 : 16-row band
    const int wc = warp & 3;      // 0..3 : 16-col band

    const float4* A4 = (const float4*)(x + (size_t)(bz * L_ + ti * TILE) * D_);
    const float4* B4 = (const float4*)(x + (size_t)(bz * L_ + tj * TILE) * D_);
    const float4* W4 = (const float4*)W;   // W[:256] = w1

    // ---- stage all gmem loads: 8 float4 per matrix per thread ----
    float4 ra[8], rb[8];
    #pragma unroll
    for (int i = 0; i < 8; i++) {
        int lin = i * THREADS + tid;       // 0..4095
        int row = lin >> 6;                // 0..63
        int c4  = lin & 63;
        ra[i] = A4[row * 64 + c4];
        rb[i] = B4[row * 64 + c4];
    }

    // ---- packed split-bf16 convert + STS ----
    #pragma unroll
    for (int i = 0; i < 8; i++) {
        int lin = i * THREADS + tid;
        int row = lin >> 6;
        int c4  = lin & 63;
        float4 wv = __ldg(&W4[c4]);

        float av[4] = {ra[i].x * wv.x, ra[i].y * wv.y,
                       ra[i].z * wv.z, ra[i].w * wv.w};
        float bv[4] = {rb[i].x, rb[i].y, rb[i].z, rb[i].w};

        uint2 ahi, alo, bhi, blo;
        split4(av, ahi, alo);
        split4(bv, bhi, blo);

        int off = row * SST + c4 * 4;
        *(uint2*)&sAhi[off] = ahi;
        *(uint2*)&sAlo[off] = alo;
        *(uint2*)&sBhi[off] = bhi;
        *(uint2*)&sBlo[off] = blo;
    }
    __syncthreads();

    // ---- 48 uninterrupted wmma k-steps (warp tile 16x16) ----
    wmma::fragment<wmma::accumulator, 16, 16, 16, float> acc;
    wmma::fill_fragment(acc, 0.0f);

    const __nv_bfloat16* pa[3] = {sAhi, sAhi, sAlo};
    const __nv_bfloat16* pb[3] = {sBhi, sBlo, sBhi};

    #pragma unroll
    for (int p = 0; p < 3; p++) {
        const __nv_bfloat16* Abase = pa[p] + (wr * 16) * SST;
        const __nv_bfloat16* Bbase = pb[p] + (wc * 16) * SST;
        #pragma unroll
        for (int kk = 0; kk < D_; kk += 16) {
            wmma::fragment<wmma::matrix_a, 16, 16, 16, __nv_bfloat16, wmma::row_major> af;
            wmma::fragment<wmma::matrix_b, 16, 16, 16, __nv_bfloat16, wmma::col_major> bf;
            wmma::load_matrix_sync(af, Abase + kk, SST);
            wmma::load_matrix_sync(bf, Bbase + kk, SST);
            wmma::mma_sync(acc, af, bf, acc);
        }
    }

    // ---- epilogue ----
    const float bias = bias_p[0];
    #pragma unroll
    for (int t = 0; t < acc.num_elements; t++)
        acc.x[t] += bias;
    int gi = ti * TILE + wr * 16;
    int gj = tj * TILE + wc * 16;
    float* dst = out + (size_t)bz * L_ * L_ + (size_t)gi * L_ + gj;
    wmma::store_matrix_sync(dst, acc, L_, wmma::mem_row_major);
}

// ---------------------------------------------------------------------------
// d_in[0] = inputs f32 (2,512,256), d_in[1] = W f32 (512,1), d_in[2] = b f32 (1,)
// d_out   = f32 (2,512,512,1)
// ---------------------------------------------------------------------------
extern "C" void kernel_launch(void* const* d_in, const int* in_sizes, int n_in,
                              void* d_out, int out_size) {
    const float* x    = (const float*)d_in[0];
    const float* W    = (const float*)d_in[1];
    const float* bptr = (const float*)d_in[2];
    float* out = (float*)d_out;

    static bool attr_set = false;
    if (!attr_set) {
        cudaFuncSetAttribute(fused_pairwise_kernel,
                             cudaFuncAttributeMaxDynamicSharedMemorySize, SMEM_BYTES);
        attr_set = true;
    }

    dim3 grid(L_ / TILE, L_ / TILE, B_);   // (8, 8, 2) = 128 CTAs
    fused_pairwise_kernel<<<grid, THREADS, SMEM_BYTES>>>(x, W, bptr, out);
}

// round 7
// speedup vs baseline: 1.4301x; 1.4301x over previous
#include <cuda_runtime.h>
#include <cuda_bf16.h>
#include <mma.h>
#include <cstdint>

using namespace nvcuda;

// Fixed shapes
#define B_      2
#define L_      512
#define D_      256
#define TILE    64
#define THREADS 512
#define SST     264                      // 256 + 8 pad bf16 (528B rows)
#define TILE_ELEMS (TILE * SST)
#define SMEM_BYTES (4 * TILE_ELEMS * 2)  // 135168 B

// out[b,i,j] = sum_d x[b,i,d]*w1[d]*x[b,j,d] + bias
// (lin_i - lin_j cancels under (P+P^T)/2 symmetrization; w2 dead.)
// split-bf16 3-product: a*x ≈ ahi*xhi + ahi*xlo + alo*xhi (rel ~2^-18)

__device__ __forceinline__ uint32_t cvt2(float a, float b) {
    __nv_bfloat162 h = __floats2bfloat162_rn(a, b);
    return *reinterpret_cast<uint32_t*>(&h);
}
__device__ __forceinline__ void split4(const float* v, uint2& hi, uint2& lo) {
    uint32_t h01 = cvt2(v[0], v[1]);
    uint32_t h23 = cvt2(v[2], v[3]);
    float f0 = __uint_as_float(h01 << 16);
    float f1 = __uint_as_float(h01 & 0xFFFF0000u);
    float f2 = __uint_as_float(h23 << 16);
    float f3 = __uint_as_float(h23 & 0xFFFF0000u);
    hi.x = h01; hi.y = h23;
    lo.x = cvt2(v[0] - f0, v[1] - f1);
    lo.y = cvt2(v[2] - f2, v[3] - f3);
}

__global__ __launch_bounds__(THREADS, 1)
void fused_pairwise_kernel(const float* __restrict__ x,
                           const float* __restrict__ W,
                           const float* __restrict__ bias_p,
                           float* __restrict__ out) {
    extern __shared__ __align__(16) __nv_bfloat16 smem[];
    __nv_bfloat16* sAhi = smem;
    __nv_bfloat16* sAlo = smem + TILE_ELEMS;
    __nv_bfloat16* sBhi = smem + 2 * TILE_ELEMS;
    __nv_bfloat16* sBlo = smem + 3 * TILE_ELEMS;

    const int bz  = blockIdx.z;
    const int ti  = blockIdx.y;
    const int tj  = blockIdx.x;
    const int tid = threadIdx.x;
    const int warp = tid >> 5;

    const float4* A4 = (const float4*)(x + (size_t)(bz * L_ + ti * TILE) * D_);
    const float4* B4 = (const float4*)(x + (size_t)(bz * L_ + tj * TILE) * D_);
    const float4* W4 = (const float4*)W;   // W[:256] = w1

    // ---- stage gmem: 8 float4 per matrix per thread ----
    float4 ra[8], rb[8];
    #pragma unroll
    for (int i = 0; i < 8; i++) {
        int lin = i * THREADS + tid;       // 0..4095
        int row = lin >> 6;
        int c4  = lin & 63;
        ra[i] = A4[row * 64 + c4];
        rb[i] = B4[row * 64 + c4];
    }

    // ---- packed split-bf16 convert + STS ----
    #pragma unroll
    for (int i = 0; i < 8; i++) {
        int lin = i * THREADS + tid;
        int row = lin >> 6;
        int c4  = lin & 63;
        float4 wv = __ldg(&W4[c4]);

        float av[4] = {ra[i].x * wv.x, ra[i].y * wv.y,
                       ra[i].z * wv.z, ra[i].w * wv.w};
        float bv[4] = {rb[i].x, rb[i].y, rb[i].z, rb[i].w};

        uint2 ahi, alo, bhi, blo;
        split4(av, ahi, alo);
        split4(bv, bhi, blo);

        int off = row * SST + c4 * 4;
        *(uint2*)&sAhi[off] = ahi;
        *(uint2*)&sAlo[off] = alo;
        *(uint2*)&sBhi[off] = bhi;
        *(uint2*)&sBlo[off] = blo;
    }
    __syncthreads();

    // ---- MMA: warps 0-3 only, 2x2 layout, 32x32 per warp ----
    if (warp >= 4) return;

    const int wr = (warp >> 1) & 1;   // row half
    const int wc = warp & 1;          // col half

    wmma::fragment<wmma::accumulator, 16, 16, 16, float> acc[2][2];
    #pragma unroll
    for (int r = 0; r < 2; r++)
        #pragma unroll
        for (int c = 0; c < 2; c++)
            wmma::fill_fragment(acc[r][c], 0.0f);

    const __nv_bfloat16* Ah = sAhi + (wr * 32) * SST;
    const __nv_bfloat16* Al = sAlo + (wr * 32) * SST;
    const __nv_bfloat16* Bh = sBhi + (wc * 32) * SST;
    const __nv_bfloat16* Bl = sBlo + (wc * 32) * SST;

    #pragma unroll
    for (int kk = 0; kk < D_; kk += 16) {
        wmma::fragment<wmma::matrix_a, 16, 16, 16, __nv_bfloat16, wmma::row_major> ah[2], al[2];
        wmma::fragment<wmma::matrix_b, 16, 16, 16, __nv_bfloat16, wmma::col_major> bh[2], bl[2];
        #pragma unroll
        for (int r = 0; r < 2; r++) {
            wmma::load_matrix_sync(ah[r], Ah + r * 16 * SST + kk, SST);
            wmma::load_matrix_sync(al[r], Al + r * 16 * SST + kk, SST);
        }
        #pragma unroll
        for (int c = 0; c < 2; c++) {
            wmma::load_matrix_sync(bh[c], Bh + c * 16 * SST + kk, SST);
            wmma::load_matrix_sync(bl[c], Bl + c * 16 * SST + kk, SST);
        }
        // 12 MMAs: acc += ah*bh + ah*bl + al*bh   (fragment reuse across products)
        #pragma unroll
        for (int r = 0; r < 2; r++) {
            #pragma unroll
            for (int c = 0; c < 2; c++) {
                wmma::mma_sync(acc[r][c], ah[r], bh[c], acc[r][c]);
                wmma::mma_sync(acc[r][c], ah[r], bl[c], acc[r][c]);
                wmma::mma_sync(acc[r][c], al[r], bh[c], acc[r][c]);
            }
        }
    }

    // ---- epilogue ----
    const float bias = bias_p[0];
    #pragma unroll
    for (int r = 0; r < 2; r++) {
        #pragma unroll
        for (int c = 0; c < 2; c++) {
            #pragma unroll
            for (int t = 0; t < acc[r][c].num_elements; t++)
                acc[r][c].x[t] += bias;
            int gi = ti * TILE + wr * 32 + r * 16;
            int gj = tj * TILE + wc * 32 + c * 16;
            float* dst = out + (size_t)bz * L_ * L_ + (size_t)gi * L_ + gj;
            wmma::store_matrix_sync(dst, acc[r][c], L_, wmma::mem_row_major);
        }
    }
}

// ---------------------------------------------------------------------------
// d_in[0] = inputs f32 (2,512,256), d_in[1] = W f32 (512,1), d_in[2] = b f32 (1,)
// d_out   = f32 (2,512,512,1)
// ---------------------------------------------------------------------------
extern "C" void kernel_launch(void* const* d_in, const int* in_sizes, int n_in,
                              void* d_out, int out_size) {
    const float* x    = (const float*)d_in[0];
    const float* W    = (const float*)d_in[1];
    const float* bptr = (const float*)d_in[2];
    float* out = (float*)d_out;

    static bool attr_set = false;
    if (!attr_set) {
        cudaFuncSetAttribute(fused_pairwise_kernel,
                             cudaFuncAttributeMaxDynamicSharedMemorySize, SMEM_BYTES);
        attr_set = true;
    }

    dim3 grid(L_ / TILE, L_ / TILE, B_);   // (8, 8, 2) = 128 CTAs
    fused_pairwise_kernel<<<grid, THREADS, SMEM_BYTES>>>(x, W, bptr, out);
}

// round 8
// speedup vs baseline: 1.4615x; 1.0220x over previous
#include <cuda_runtime.h>
#include <cuda_bf16.h>
#include <mma.h>
#include <cstdint>

using namespace nvcuda;

// Fixed shapes
#define B_      2
#define L_      512
#define D_      256
#define KH      (D_ / 2)                 // 128 per K-half
#define TILE    64
#define THREADS 512
#define SST     264                      // 256 + 8 pad bf16 (528B rows)
#define TILE_ELEMS (TILE * SST)
#define SMEM_BYTES (4 * TILE_ELEMS * 2)  // 135168 B
#define PST     68                       // partial-buffer stride (floats), 272B rows

// out[b,i,j] = sum_d x[b,i,d]*w1[d]*x[b,j,d] + bias
// (lin_i - lin_j cancels under (P+P^T)/2 symmetrization; w2 dead.)
// split-bf16 3-product: a*x ≈ ahi*xhi + ahi*xlo + alo*xhi (rel ~2^-18)

__device__ __forceinline__ uint32_t cvt2(float a, float b) {
    __nv_bfloat162 h = __floats2bfloat162_rn(a, b);
    return *reinterpret_cast<uint32_t*>(&h);
}
__device__ __forceinline__ void split4(const float* v, uint2& hi, uint2& lo) {
    uint32_t h01 = cvt2(v[0], v[1]);
    uint32_t h23 = cvt2(v[2], v[3]);
    float f0 = __uint_as_float(h01 << 16);
    float f1 = __uint_as_float(h01 & 0xFFFF0000u);
    float f2 = __uint_as_float(h23 << 16);
    float f3 = __uint_as_float(h23 & 0xFFFF0000u);
    hi.x = h01; hi.y = h23;
    lo.x = cvt2(v[0] - f0, v[1] - f1);
    lo.y = cvt2(v[2] - f2, v[3] - f3);
}

__global__ __launch_bounds__(THREADS, 1)
void fused_pairwise_kernel(const float* __restrict__ x,
                           const float* __restrict__ W,
                           const float* __restrict__ bias_p,
                           float* __restrict__ out) {
    extern __shared__ __align__(16) __nv_bfloat16 smem[];
    __nv_bfloat16* sAhi = smem;
    __nv_bfloat16* sAlo = smem + TILE_ELEMS;
    __nv_bfloat16* sBhi = smem + 2 * TILE_ELEMS;
    __nv_bfloat16* sBlo = smem + 3 * TILE_ELEMS;
    // partial buffers reuse operand smem after the MMA phase
    float* P0 = (float*)smem;                       // 64 x PST floats (17408 B)
    float* P1 = (float*)(smem + TILE_ELEMS);        // second half, safely disjoint

    const int bz  = blockIdx.z;
    const int ti  = blockIdx.y;
    const int tj  = blockIdx.x;
    const int tid = threadIdx.x;
    const int warp = tid >> 5;

    const float4* A4 = (const float4*)(x + (size_t)(bz * L_ + ti * TILE) * D_);
    const float4* B4 = (const float4*)(x + (size_t)(bz * L_ + tj * TILE) * D_);
    const float4* W4 = (const float4*)W;   // W[:256] = w1

    // ---- stage gmem: 8 float4 per matrix per thread ----
    float4 ra[8], rb[8];
    #pragma unroll
    for (int i = 0; i < 8; i++) {
        int lin = i * THREADS + tid;       // 0..4095
        int row = lin >> 6;
        int c4  = lin & 63;
        ra[i] = A4[row * 64 + c4];
        rb[i] = B4[row * 64 + c4];
    }

    // ---- packed split-bf16 convert + STS ----
    #pragma unroll
    for (int i = 0; i < 8; i++) {
        int lin = i * THREADS + tid;
        int row = lin >> 6;
        int c4  = lin & 63;
        float4 wv = __ldg(&W4[c4]);

        float av[4] = {ra[i].x * wv.x, ra[i].y * wv.y,
                       ra[i].z * wv.z, ra[i].w * wv.w};
        float bv[4] = {rb[i].x, rb[i].y, rb[i].z, rb[i].w};

        uint2 ahi, alo, bhi, blo;
        split4(av, ahi, alo);
        split4(bv, bhi, blo);

        int off = row * SST + c4 * 4;
        *(uint2*)&sAhi[off] = ahi;
        *(uint2*)&sAlo[off] = alo;
        *(uint2*)&sBhi[off] = bhi;
        *(uint2*)&sBlo[off] = blo;
    }
    __syncthreads();

    // ---- MMA: warps 0-7.  2x2 spatial grid x 2 K-halves, 32x32 per warp ----
    wmma::fragment<wmma::accumulator, 16, 16, 16, float> acc[2][2];
    const int wr = (warp >> 1) & 1;   // row half
    const int wc = warp & 1;          // col half
    const int kh = warp >> 2;         // K half (0 or 1)

    if (warp < 8) {
        #pragma unroll
        for (int r = 0; r < 2; r++)
            #pragma unroll
            for (int c = 0; c < 2; c++)
                wmma::fill_fragment(acc[r][c], 0.0f);

        const int kbase = kh * KH;
        const __nv_bfloat16* Ah = sAhi + (wr * 32) * SST + kbase;
        const __nv_bfloat16* Al = sAlo + (wr * 32) * SST + kbase;
        const __nv_bfloat16* Bh = sBhi + (wc * 32) * SST + kbase;
        const __nv_bfloat16* Bl = sBlo + (wc * 32) * SST + kbase;

        #pragma unroll
        for (int kk = 0; kk < KH; kk += 16) {
            wmma::fragment<wmma::matrix_a, 16, 16, 16, __nv_bfloat16, wmma::row_major> ah[2], al[2];
            wmma::fragment<wmma::matrix_b, 16, 16, 16, __nv_bfloat16, wmma::col_major> bh[2], bl[2];
            #pragma unroll
            for (int r = 0; r < 2; r++) {
                wmma::load_matrix_sync(ah[r], Ah + r * 16 * SST + kk, SST);
                wmma::load_matrix_sync(al[r], Al + r * 16 * SST + kk, SST);
            }
            #pragma unroll
            for (int c = 0; c < 2; c++) {
                wmma::load_matrix_sync(bh[c], Bh + c * 16 * SST + kk, SST);
                wmma::load_matrix_sync(bl[c], Bl + c * 16 * SST + kk, SST);
            }
            #pragma unroll
            for (int r = 0; r < 2; r++) {
                #pragma unroll
                for (int c = 0; c < 2; c++) {
                    wmma::mma_sync(acc[r][c], ah[r], bh[c], acc[r][c]);
                    wmma::mma_sync(acc[r][c], ah[r], bl[c], acc[r][c]);
                    wmma::mma_sync(acc[r][c], al[r], bh[c], acc[r][c]);
                }
            }
        }
    }
    __syncthreads();   // all operand reads done; smem becomes partial buffers

    // ---- store partials to smem ----
    if (warp < 8) {
        float* P = kh ? P1 : P0;
        #pragma unroll
        for (int r = 0; r < 2; r++)
            #pragma unroll
            for (int c = 0; c < 2; c++)
                wmma::store_matrix_sync(P + (wr * 32 + r * 16) * PST + wc * 32 + c * 16,
                                        acc[r][c], PST, wmma::mem_row_major);
    }
    __syncthreads();

    // ---- reduce + bias + STG: 4096 elems / 512 threads = 2 float4 each ----
    const float bias = bias_p[0];
    float* obase = out + (size_t)bz * L_ * L_ + (size_t)(ti * TILE) * L_ + tj * TILE;
    #pragma unroll
    for (int i = 0; i < 2; i++) {
        int lin = i * THREADS + tid;       // 0..1023 (float4 units)
        int row = lin >> 4;                // 0..63
        int c4  = lin & 15;                // 16 float4 per 64-col row
        float4 v0 = *(float4*)&P0[row * PST + c4 * 4];
        float4 v1 = *(float4*)&P1[row * PST + c4 * 4];
        float4 o;
        o.x = v0.x + v1.x + bias;
        o.y = v0.y + v1.y + bias;
        o.z = v0.z + v1.z + bias;
        o.w = v0.w + v1.w + bias;
        *(float4*)(obase + (size_t)row * L_ + c4 * 4) = o;
    }
}

// ---------------------------------------------------------------------------
// d_in[0] = inputs f32 (2,512,256), d_in[1] = W f32 (512,1), d_in[2] = b f32 (1,)
// d_out   = f32 (2,512,512,1)
// ---------------------------------------------------------------------------
extern "C" void kernel_launch(void* const* d_in, const int* in_sizes, int n_in,
                              void* d_out, int out_size) {
    const float* x    = (const float*)d_in[0];
    const float* W    = (const float*)d_in[1];
    const float* bptr = (const float*)d_in[2];
    float* out = (float*)d_out;

    static bool attr_set = false;
    if (!attr_set) {
        cudaFuncSetAttribute(fused_pairwise_kernel,
                             cudaFuncAttributeMaxDynamicSharedMemorySize, SMEM_BYTES);
        attr_set = true;
    }

    dim3 grid(L_ / TILE, L_ / TILE, B_);   // (8, 8, 2) = 128 CTAs
    fused_pairwise_kernel<<<grid, THREADS, SMEM_BYTES>>>(x, W, bptr, out);
}